// round 12
// baseline (speedup 1.0000x reference)
#include <cuda_runtime.h>
#include <cuda_bf16.h>
#include <cstdint>

#define NNODES 50000
#define NEDGES 150000
#define EPLUS  (NEDGES + NNODES)   // edges + self loops = 200000
#define NGRAPH 1024
#define INDIM  78
#define KP1    128                 // layer-1 K padded to 128
#define HID    640
#define HEADS  10
#define C1     64
#define NEGSLOPE 0.2f

// ---------------- scratch (static __device__ — no allocations allowed) -----
__device__ __align__(128) float g_bufA[(size_t)NNODES * HID];
__device__ __align__(128) float g_bufB[(size_t)NNODES * HID];
__device__ float g_dinv[NNODES];
__device__ int   g_rowptr[NNODES + 1];
__device__ int   g_cntbuf[NNODES];
__device__ int   g_csr_src[EPLUS];
__device__ int   g_gmax[NGRAPH * HID];
__device__ float g_gsum[NGRAPH * HID];
__device__ float g_cnt [NGRAPH];
// bf16 split buffers
__device__ __align__(128) __nv_bfloat16 g_xhi[(size_t)NNODES * KP1];
__device__ __align__(128) __nv_bfloat16 g_xlo[(size_t)NNODES * KP1];
__device__ __align__(128) __nv_bfloat16 g_hhi[(size_t)NNODES * HID];
__device__ __align__(128) __nv_bfloat16 g_hlo[(size_t)NNODES * HID];
__device__ __align__(128) __nv_bfloat16 g_w1lhi[HID * KP1], g_w1llo[HID * KP1];
__device__ __align__(128) __nv_bfloat16 g_w1rhi[HID * KP1], g_w1rlo[HID * KP1];
__device__ __align__(128) __nv_bfloat16 g_w2lhi[HID * HID], g_w2llo[HID * HID];
__device__ __align__(128) __nv_bfloat16 g_w2rhi[HID * HID], g_w2rlo[HID * HID];
__device__ __align__(128) __nv_bfloat16 g_wghi [HID * HID], g_wglo [HID * HID];

// ---------------- helpers --------------------------------------------------
__device__ __forceinline__ uint32_t smem_u32(const void* p) {
    return (uint32_t)__cvta_generic_to_shared(p);
}
#define LDSM4(r0, r1, r2, r3, addr) \
    asm volatile("ldmatrix.sync.aligned.m8n8.x4.shared.b16 {%0,%1,%2,%3}, [%4];" \
                 : "=r"(r0), "=r"(r1), "=r"(r2), "=r"(r3) : "r"(addr))
#define MMA16816(c, a0, a1, a2, a3, b0, b1) \
    asm volatile("mma.sync.aligned.m16n8k16.row.col.f32.bf16.bf16.f32 " \
                 "{%0,%1,%2,%3}, {%4,%5,%6,%7}, {%8,%9}, {%0,%1,%2,%3};" \
                 : "+f"((c)[0]), "+f"((c)[1]), "+f"((c)[2]), "+f"((c)[3]) \
                 : "r"(a0), "r"(a1), "r"(a2), "r"(a3), "r"(b0), "r"(b1))
__device__ __forceinline__ void cpasync16(uint32_t dst, const void* src, int sz) {
    asm volatile("cp.async.cg.shared.global [%0], [%1], 16, %2;"
                 :: "r"(dst), "l"(src), "r"(sz));
}
#define CP_COMMIT asm volatile("cp.async.commit_group;")
#define CP_WAIT1  asm volatile("cp.async.wait_group 1;")
#define CP_WAIT0  asm volatile("cp.async.wait_group 0;")

// ---------------- fills ----------------------------------------------------
__global__ void k_fill_f(float* p, float v, int n) {
    int i = blockIdx.x * blockDim.x + threadIdx.x;
    if (i < n) p[i] = v;
}
__global__ void k_fill_i(int* p, int v, int n) {
    int i = blockIdx.x * blockDim.x + threadIdx.x;
    if (i < n) p[i] = v;
}

// ---------------- CSR build ------------------------------------------------
__global__ void k_count(const int* __restrict__ ei, int* __restrict__ cnt) {
    int e = blockIdx.x * blockDim.x + threadIdx.x;
    if (e >= EPLUS) return;
    int d = (e < NEDGES) ? ei[NEDGES + e] : e - NEDGES;
    atomicAdd(&cnt[d], 1);
}
__global__ void k_scan(const int* __restrict__ cnt, int* __restrict__ rowptr) {
    __shared__ int sh[1024];
    __shared__ int carry;
    if (threadIdx.x == 0) carry = 0;
    __syncthreads();
    for (int base = 0; base < NNODES; base += 1024) {
        int i = base + threadIdx.x;
        int v = (i < NNODES) ? cnt[i] : 0;
        sh[threadIdx.x] = v;
        __syncthreads();
        for (int off = 1; off < 1024; off <<= 1) {
            int t = (threadIdx.x >= off) ? sh[threadIdx.x - off] : 0;
            __syncthreads();
            sh[threadIdx.x] += t;
            __syncthreads();
        }
        if (i < NNODES) rowptr[i] = carry + sh[threadIdx.x] - v;
        __syncthreads();
        if (threadIdx.x == 1023) carry += sh[1023];
        __syncthreads();
    }
    if (threadIdx.x == 0) rowptr[NNODES] = EPLUS;
}
__global__ void k_scatter(const int* __restrict__ ei, const int* __restrict__ rowptr,
                          int* __restrict__ fill, int* __restrict__ csr_src) {
    int e = blockIdx.x * blockDim.x + threadIdx.x;
    if (e >= EPLUS) return;
    int s, d;
    if (e < NEDGES) { s = ei[e]; d = ei[NEDGES + e]; }
    else            { s = d = e - NEDGES; }
    int pos = rowptr[d] + atomicAdd(&fill[d], 1);
    csr_src[pos] = s;
}
__global__ void k_dinv(const int* __restrict__ rowptr, float* __restrict__ dinv) {
    int n = blockIdx.x * blockDim.x + threadIdx.x;
    if (n >= NNODES) return;
    dinv[n] = rsqrtf((float)(rowptr[n + 1] - rowptr[n]));   // >=1 (self loop)
}

// ---------------- bf16 hi/lo split prep ------------------------------------
__global__ void k_split(const float* __restrict__ src,
                        __nv_bfloat16* __restrict__ hi, __nv_bfloat16* __restrict__ lo,
                        int M, int K, int Kp)
{
    int idx = blockIdx.x * blockDim.x + threadIdx.x;
    if (idx >= M * Kp) return;
    int r = idx / Kp, k = idx - r * Kp;
    float v = (k < K) ? src[(size_t)r * K + k] : 0.f;
    __nv_bfloat16 h = __float2bfloat16(v);
    hi[idx] = h;
    lo[idx] = __float2bfloat16(v - __bfloat162float(h));
}
__global__ void k_splitT(const float* __restrict__ W,
                         __nv_bfloat16* __restrict__ hi, __nv_bfloat16* __restrict__ lo,
                         int K, int N, int Kp)
{
    int idx = blockIdx.x * blockDim.x + threadIdx.x;
    if (idx >= N * Kp) return;
    int n = idx / Kp, k = idx - n * Kp;
    float v = (k < K) ? W[(size_t)k * N + n] : 0.f;
    __nv_bfloat16 h = __float2bfloat16(v);
    hi[idx] = h;
    lo[idx] = __float2bfloat16(v - __bfloat162float(h));
}

// ---------------- split-bf16 HMMA GEMM, cp.async double buffer -------------
#define STG_T   10240               // bytes per tensor per stage (128*80)
#define STG_ALL 40960               // bytes per stage

__global__ __launch_bounds__(256, 2)
void k_hgemm(const __nv_bfloat16* __restrict__ Ahi, const __nv_bfloat16* __restrict__ Alo,
             const __nv_bfloat16* __restrict__ Bhi, const __nv_bfloat16* __restrict__ Blo,
             float* __restrict__ C, int M, int N, int K)
{
    extern __shared__ __align__(128) char smem[];
    const uint32_t sb = smem_u32(smem);
    const int tid = threadIdx.x, lane = tid & 31, wid = tid >> 5;
    const int wm = wid & 3, wn = wid >> 2;
    const int bm = blockIdx.y * 128, bn = blockIdx.x * 128;

    float c[2][8][4];
    #pragma unroll
    for (int i = 0; i < 2; i++)
        #pragma unroll
        for (int j = 0; j < 8; j++)
            #pragma unroll
            for (int q = 0; q < 4; q++) c[i][j][q] = 0.f;

    const int row = tid >> 1, half = tid & 1;
    const bool va = (bm + row) < M;
    const int szA = va ? 16 : 0;
    const char* gAh = (const char*)(Ahi + (size_t)(bm + row) * K) + half * 32;
    const char* gAl = (const char*)(Alo + (size_t)(bm + row) * K) + half * 32;
    const char* gBh = (const char*)(Bhi + (size_t)(bn + row) * K) + half * 32;
    const char* gBl = (const char*)(Blo + (size_t)(bn + row) * K) + half * 32;
    const uint32_t dOff = (uint32_t)(row * 80 + half * 32);

#define LOAD_STAGE(s, k0) do {                                              \
        uint32_t b_ = sb + (uint32_t)((s) & 1) * STG_ALL;                   \
        size_t kb_ = (size_t)(k0) * 2;                                      \
        cpasync16(b_ + 0 * STG_T + dOff,      gAh + kb_,      szA);         \
        cpasync16(b_ + 0 * STG_T + dOff + 16, gAh + kb_ + 16, szA);         \
        cpasync16(b_ + 1 * STG_T + dOff,      gAl + kb_,      szA);         \
        cpasync16(b_ + 1 * STG_T + dOff + 16, gAl + kb_ + 16, szA);         \
        cpasync16(b_ + 2 * STG_T + dOff,      gBh + kb_,      16);          \
        cpasync16(b_ + 2 * STG_T + dOff + 16, gBh + kb_ + 16, 16);          \
        cpasync16(b_ + 3 * STG_T + dOff,      gBl + kb_,      16);          \
        cpasync16(b_ + 3 * STG_T + dOff + 16, gBl + kb_ + 16, 16);          \
    } while (0)

    const uint32_t a_mr = (lane & 7) + ((lane >> 3) & 1) * 8;
    const uint32_t a_kc = (lane >> 4) * 8;
    const uint32_t b_nr = ((lane >> 4) & 1) * 8 + (lane & 7);
    const uint32_t b_kc = ((lane >> 3) & 1) * 8;

    const int nst = K >> 5;
    LOAD_STAGE(0, 0);
    CP_COMMIT;
    for (int s = 0; s < nst; s++) {
        if (s + 1 < nst) { LOAD_STAGE(s + 1, (s + 1) << 5); CP_COMMIT; CP_WAIT1; }
        else             { CP_WAIT0; }
        __syncthreads();

        uint32_t base = sb + (uint32_t)(s & 1) * STG_ALL;
        #pragma unroll
        for (int ksub = 0; ksub < 2; ksub++) {
            uint32_t ko = ksub * 32;
            uint32_t ah[2][4], al[2][4];
            #pragma unroll
            for (int mt = 0; mt < 2; mt++) {
                uint32_t aaddr = (uint32_t)((wm * 32 + mt * 16 + a_mr) * 80) + ko + a_kc * 2;
                LDSM4(ah[mt][0], ah[mt][1], ah[mt][2], ah[mt][3], base + 0 * STG_T + aaddr);
                LDSM4(al[mt][0], al[mt][1], al[mt][2], al[mt][3], base + 1 * STG_T + aaddr);
            }
            #pragma unroll
            for (int bg = 0; bg < 4; bg++) {
                uint32_t baddr = (uint32_t)((wn * 64 + bg * 16 + b_nr) * 80) + ko + b_kc * 2;
                uint32_t bh0, bh1, bh2, bh3, bl0, bl1, bl2, bl3;
                LDSM4(bh0, bh1, bh2, bh3, base + 2 * STG_T + baddr);
                LDSM4(bl0, bl1, bl2, bl3, base + 3 * STG_T + baddr);
                #pragma unroll
                for (int mt = 0; mt < 2; mt++) {
                    float* c0 = c[mt][bg * 2];
                    float* c1 = c[mt][bg * 2 + 1];
                    MMA16816(c0, ah[mt][0], ah[mt][1], ah[mt][2], ah[mt][3], bh0, bh1);
                    MMA16816(c0, ah[mt][0], ah[mt][1], ah[mt][2], ah[mt][3], bl0, bl1);
                    MMA16816(c0, al[mt][0], al[mt][1], al[mt][2], al[mt][3], bh0, bh1);
                    MMA16816(c1, ah[mt][0], ah[mt][1], ah[mt][2], ah[mt][3], bh2, bh3);
                    MMA16816(c1, ah[mt][0], ah[mt][1], ah[mt][2], ah[mt][3], bl2, bl3);
                    MMA16816(c1, al[mt][0], al[mt][1], al[mt][2], al[mt][3], bh2, bh3);
                }
            }
        }
        __syncthreads();
    }
#undef LOAD_STAGE

    const int rbase = bm + wm * 32 + (lane >> 2);
    const int cbase = bn + wn * 64 + (lane & 3) * 2;
    #pragma unroll
    for (int mt = 0; mt < 2; mt++) {
        #pragma unroll
        for (int nt = 0; nt < 8; nt++) {
            int rr = rbase + mt * 16;
            int cc = cbase + nt * 8;
            if (rr < M)
                *(float2*)&C[(size_t)rr * N + cc] = make_float2(c[mt][nt][0], c[mt][nt][1]);
            if (rr + 8 < M)
                *(float2*)&C[(size_t)(rr + 8) * N + cc] = make_float2(c[mt][nt][2], c[mt][nt][3]);
        }
    }
}

// ---------------- fused GATv2 layer 1: online softmax + aggregate ----------
// warp per (node, head); xl[src] gathered ONCE per edge.
// out: bias + ELU + bf16 hi/lo split.
__global__ void k_gat64(const float* __restrict__ xl,
                        const float* __restrict__ xr,
                        const int* __restrict__ rowptr,
                        const int* __restrict__ csr_src,
                        const float* __restrict__ att,
                        const float* __restrict__ bias,
                        __nv_bfloat16* __restrict__ ohi,
                        __nv_bfloat16* __restrict__ olo)
{
    int gw = (blockIdx.x * blockDim.x + threadIdx.x) >> 5;
    int lane = threadIdx.x & 31;
    if (gw >= NNODES * HEADS) return;
    int n = gw / HEADS, h = gw - n * HEADS;
    int r0 = rowptr[n], r1 = rowptr[n + 1];
    int cb = h * C1 + lane * 2;

    float2 xr2 = *(const float2*)&xr[(size_t)n * HID + cb];
    float2 at2 = *(const float2*)&att[cb];

    float m = -3.4e38f, den = 0.f, a0 = 0.f, a1 = 0.f;
    for (int i = r0; i < r1; i++) {
        int s = csr_src[i];
        float2 x2 = *(const float2*)&xl[(size_t)s * HID + cb];
        float v0 = x2.x + xr2.x; v0 = v0 > 0.f ? v0 : NEGSLOPE * v0;
        float v1 = x2.y + xr2.y; v1 = v1 > 0.f ? v1 : NEGSLOPE * v1;
        float t = v0 * at2.x + v1 * at2.y;
        #pragma unroll
        for (int o = 16; o > 0; o >>= 1)
            t += __shfl_xor_sync(0xffffffffu, t, o);
        float mn = fmaxf(m, t);
        float sc = expf(m - mn);
        float ex = expf(t - mn);
        den = den * sc + ex;
        a0  = a0  * sc + ex * x2.x;
        a1  = a1  * sc + ex * x2.y;
        m = mn;
    }
    float inv = 1.f / den;
    float o0 = a0 * inv + bias[cb];
    float o1 = a1 * inv + bias[cb + 1];
    o0 = o0 > 0.f ? o0 : expm1f(o0);
    o1 = o1 > 0.f ? o1 : expm1f(o1);
    __nv_bfloat16 h0 = __float2bfloat16(o0), h1 = __float2bfloat16(o1);
    __nv_bfloat162 hp; hp.x = h0; hp.y = h1;
    __nv_bfloat162 lp;
    lp.x = __float2bfloat16(o0 - __bfloat162float(h0));
    lp.y = __float2bfloat16(o1 - __bfloat162float(h1));
    *(__nv_bfloat162*)&ohi[(size_t)n * HID + cb] = hp;
    *(__nv_bfloat162*)&olo[(size_t)n * HID + cb] = lp;
}

// ---------------- fused GATv2 layer 2 (H=1, C=640): warp per node ----------
__global__ void k_gat640(const float* __restrict__ xl,
                         const float* __restrict__ xr,
                         const int* __restrict__ rowptr,
                         const int* __restrict__ csr_src,
                         const float* __restrict__ att,
                         const float* __restrict__ bias,
                         __nv_bfloat16* __restrict__ ohi,
                         __nv_bfloat16* __restrict__ olo)
{
    int n = (blockIdx.x * blockDim.x + threadIdx.x) >> 5;
    int lane = threadIdx.x & 31;
    if (n >= NNODES) return;
    int r0 = rowptr[n], r1 = rowptr[n + 1];

    float4 xr4[5], at4[5];
    const float4* pr = (const float4*)(xr + (size_t)n * HID);
    const float4* pa = (const float4*)att;
    #pragma unroll
    for (int j = 0; j < 5; j++) {
        xr4[j] = pr[j * 32 + lane];
        at4[j] = pa[j * 32 + lane];
    }

    float m = -3.4e38f, den = 0.f;
    float acc[5][4];
    #pragma unroll
    for (int j = 0; j < 5; j++)
        #pragma unroll
        for (int q = 0; q < 4; q++) acc[j][q] = 0.f;

    for (int i = r0; i < r1; i++) {
        int s = csr_src[i];
        const float4* ps = (const float4*)(xl + (size_t)s * HID);
        float4 xv[5];
        float t = 0.f;
        #pragma unroll
        for (int j = 0; j < 5; j++) {
            xv[j] = ps[j * 32 + lane];
            float v;
            v = xv[j].x + xr4[j].x; v = v > 0.f ? v : NEGSLOPE * v; t += v * at4[j].x;
            v = xv[j].y + xr4[j].y; v = v > 0.f ? v : NEGSLOPE * v; t += v * at4[j].y;
            v = xv[j].z + xr4[j].z; v = v > 0.f ? v : NEGSLOPE * v; t += v * at4[j].z;
            v = xv[j].w + xr4[j].w; v = v > 0.f ? v : NEGSLOPE * v; t += v * at4[j].w;
        }
        #pragma unroll
        for (int o = 16; o > 0; o >>= 1)
            t += __shfl_xor_sync(0xffffffffu, t, o);
        float mn = fmaxf(m, t);
        float sc = expf(m - mn);
        float ex = expf(t - mn);
        den = den * sc + ex;
        #pragma unroll
        for (int j = 0; j < 5; j++) {
            acc[j][0] = acc[j][0] * sc + ex * xv[j].x;
            acc[j][1] = acc[j][1] * sc + ex * xv[j].y;
            acc[j][2] = acc[j][2] * sc + ex * xv[j].z;
            acc[j][3] = acc[j][3] * sc + ex * xv[j].w;
        }
        m = mn;
    }
    float inv = 1.f / den;
    #pragma unroll
    for (int j = 0; j < 5; j++) {
        int cb = (j * 32 + lane) * 4;
        float o0 = acc[j][0] * inv + bias[cb];
        float o1 = acc[j][1] * inv + bias[cb + 1];
        float o2 = acc[j][2] * inv + bias[cb + 2];
        float o3 = acc[j][3] * inv + bias[cb + 3];
        __nv_bfloat16 h0 = __float2bfloat16(o0), h1 = __float2bfloat16(o1);
        __nv_bfloat16 h2 = __float2bfloat16(o2), h3 = __float2bfloat16(o3);
        __nv_bfloat162 hp0; hp0.x = h0; hp0.y = h1;
        __nv_bfloat162 hp1; hp1.x = h2; hp1.y = h3;
        __nv_bfloat162 lp0, lp1;
        lp0.x = __float2bfloat16(o0 - __bfloat162float(h0));
        lp0.y = __float2bfloat16(o1 - __bfloat162float(h1));
        lp1.x = __float2bfloat16(o2 - __bfloat162float(h2));
        lp1.y = __float2bfloat16(o3 - __bfloat162float(h3));
        *(__nv_bfloat162*)&ohi[(size_t)n * HID + cb]     = hp0;
        *(__nv_bfloat162*)&ohi[(size_t)n * HID + cb + 2] = hp1;
        *(__nv_bfloat162*)&olo[(size_t)n * HID + cb]     = lp0;
        *(__nv_bfloat162*)&olo[(size_t)n * HID + cb + 2] = lp1;
    }
}

// ---------------- GCN node aggregate + relu + fused pooling ----------------
__global__ void k_gcn_node(const float* __restrict__ xw,
                           const int* __restrict__ rowptr,
                           const int* __restrict__ csr_src,
                           const float* __restrict__ dinv,
                           const float* __restrict__ bg,
                           const int* __restrict__ batch,
                           int* __restrict__ gmax, float* __restrict__ gsum)
{
    int n = (blockIdx.x * blockDim.x + threadIdx.x) >> 5;
    int lane = threadIdx.x & 31;
    if (n >= NNODES) return;
    int r0 = rowptr[n], r1 = rowptr[n + 1];
    float dv = dinv[n];

    float acc[5][4];
    #pragma unroll
    for (int j = 0; j < 5; j++)
        #pragma unroll
        for (int q = 0; q < 4; q++) acc[j][q] = 0.f;

    for (int i = r0; i < r1; i++) {
        int s = csr_src[i];
        float nrm = dinv[s] * dv;
        const float4* ps = (const float4*)(xw + (size_t)s * HID);
        #pragma unroll
        for (int j = 0; j < 5; j++) {
            float4 v = ps[j * 32 + lane];
            acc[j][0] += nrm * v.x;
            acc[j][1] += nrm * v.y;
            acc[j][2] += nrm * v.z;
            acc[j][3] += nrm * v.w;
        }
    }
    int g = batch[n];
    #pragma unroll
    for (int j = 0; j < 5; j++) {
        int cb = (j * 32 + lane) * 4;
        #pragma unroll
        for (int q = 0; q < 4; q++) {
            float o = fmaxf(acc[j][q] + bg[cb + q], 0.f);
            atomicMax(&gmax[g * HID + cb + q], __float_as_int(o));
            atomicAdd(&gsum[g * HID + cb + q], o);
        }
    }
}

// ---------------- pooling tail ---------------------------------------------
__global__ void k_cnt(const int* __restrict__ batch, float* __restrict__ cnt) {
    int n = blockIdx.x * blockDim.x + threadIdx.x;
    if (n >= NNODES) return;
    atomicAdd(&cnt[batch[n]], 1.f);
}
__global__ void k_final(const int* __restrict__ gmax, const float* __restrict__ gsum,
                        const float* __restrict__ cnt, float* __restrict__ out)
{
    int idx = blockIdx.x * blockDim.x + threadIdx.x;
    if (idx >= NGRAPH * HID) return;
    int g = idx / HID, c = idx % HID;
    out[(size_t)g * (2 * HID) + c]       = __int_as_float(gmax[idx]);
    out[(size_t)g * (2 * HID) + HID + c] = gsum[idx] / fmaxf(cnt[g], 1.f);
}

// ---------------- launch ---------------------------------------------------
extern "C" void kernel_launch(void* const* d_in, const int* in_sizes, int n_in,
                              void* d_out, int out_size)
{
    const float* x     = (const float*)d_in[0];
    const int*   ei    = (const int*)d_in[1];
    const int*   batch = (const int*)d_in[2];
    const float* Wl1 = (const float*)d_in[3];
    const float* Wr1 = (const float*)d_in[4];
    const float* a1  = (const float*)d_in[5];
    const float* b1  = (const float*)d_in[6];
    const float* Wl2 = (const float*)d_in[7];
    const float* Wr2 = (const float*)d_in[8];
    const float* a2  = (const float*)d_in[9];
    const float* b2  = (const float*)d_in[10];
    const float* Wg  = (const float*)d_in[11];
    const float* bg  = (const float*)d_in[12];
    float* out = (float*)d_out;

    float *A, *B, *dinv, *gsum, *cnt;
    int *rowptr, *cntbuf, *csr_src, *gmax;
    __nv_bfloat16 *xhi, *xlo, *hhi, *hlo;
    __nv_bfloat16 *w1lhi, *w1llo, *w1rhi, *w1rlo;
    __nv_bfloat16 *w2lhi, *w2llo, *w2rhi, *w2rlo, *wghi, *wglo;
    cudaGetSymbolAddress((void**)&A,       g_bufA);
    cudaGetSymbolAddress((void**)&B,       g_bufB);
    cudaGetSymbolAddress((void**)&dinv,    g_dinv);
    cudaGetSymbolAddress((void**)&rowptr,  g_rowptr);
    cudaGetSymbolAddress((void**)&cntbuf,  g_cntbuf);
    cudaGetSymbolAddress((void**)&csr_src, g_csr_src);
    cudaGetSymbolAddress((void**)&gmax,    g_gmax);
    cudaGetSymbolAddress((void**)&gsum,    g_gsum);
    cudaGetSymbolAddress((void**)&cnt,     g_cnt);
    cudaGetSymbolAddress((void**)&xhi,     g_xhi);
    cudaGetSymbolAddress((void**)&xlo,     g_xlo);
    cudaGetSymbolAddress((void**)&hhi,     g_hhi);
    cudaGetSymbolAddress((void**)&hlo,     g_hlo);
    cudaGetSymbolAddress((void**)&w1lhi,   g_w1lhi);
    cudaGetSymbolAddress((void**)&w1llo,   g_w1llo);
    cudaGetSymbolAddress((void**)&w1rhi,   g_w1rhi);
    cudaGetSymbolAddress((void**)&w1rlo,   g_w1rlo);
    cudaGetSymbolAddress((void**)&w2lhi,   g_w2lhi);
    cudaGetSymbolAddress((void**)&w2llo,   g_w2llo);
    cudaGetSymbolAddress((void**)&w2rhi,   g_w2rhi);
    cudaGetSymbolAddress((void**)&w2rlo,   g_w2rlo);
    cudaGetSymbolAddress((void**)&wghi,    g_wghi);
    cudaGetSymbolAddress((void**)&wglo,    g_wglo);

    static bool attr_set = false;
    if (!attr_set) {
        cudaFuncSetAttribute(k_hgemm, cudaFuncAttributeMaxDynamicSharedMemorySize, 2 * STG_ALL);
        attr_set = true;
    }

    const int T = 256;
    dim3 gg(HID / 128, (NNODES + 127) / 128);            // (5, 391)
    int nb   = (NNODES + T - 1) / T;
    int epb  = (EPLUS + T - 1) / T;
    int ghb  = (NGRAPH * HID + T - 1) / T;
    int xsb  = (NNODES * KP1 + T - 1) / T;
    int w1b  = (HID * KP1 + T - 1) / T;
    int w2b  = (HID * HID + T - 1) / T;
    int nw64 = (NNODES * HEADS * 32 + T - 1) / T;        // warp per (node,head)
    int nwN  = (NNODES * 32 + T - 1) / T;                // warp per node

    // ---- CSR build (dst-sorted, incl self loops) ----
    k_fill_i<<<nb, T>>>(cntbuf, 0, NNODES);
    k_count<<<epb, T>>>(ei, cntbuf);
    k_scan<<<1, 1024>>>(cntbuf, rowptr);
    k_fill_i<<<nb, T>>>(cntbuf, 0, NNODES);
    k_scatter<<<epb, T>>>(ei, rowptr, cntbuf, csr_src);
    k_dinv<<<nb, T>>>(rowptr, dinv);

    // ---- bf16 hi/lo splits (weights + x) ----
    k_split <<<xsb, T>>>(x, xhi, xlo, NNODES, INDIM, KP1);
    k_splitT<<<w1b, T>>>(Wl1, w1lhi, w1llo, INDIM, HID, KP1);
    k_splitT<<<w1b, T>>>(Wr1, w1rhi, w1rlo, INDIM, HID, KP1);
    k_splitT<<<w2b, T>>>(Wl2, w2lhi, w2llo, HID, HID, HID);
    k_splitT<<<w2b, T>>>(Wr2, w2rhi, w2rlo, HID, HID, HID);
    k_splitT<<<w2b, T>>>(Wg,  wghi,  wglo,  HID, HID, HID);

    // ---- Layer 1: GATv2 (heads=10, C=64), fused online-softmax ----
    k_hgemm<<<gg, T, 2 * STG_ALL>>>(xhi, xlo, w1lhi, w1llo, A, NNODES, HID, KP1);
    k_hgemm<<<gg, T, 2 * STG_ALL>>>(xhi, xlo, w1rhi, w1rlo, B, NNODES, HID, KP1);
    k_gat64<<<nw64, T>>>(A, B, rowptr, csr_src, a1, b1, hhi, hlo);

    // ---- Layer 2: GATv2 (heads=1, C=640), fused online-softmax ----
    k_hgemm<<<gg, T, 2 * STG_ALL>>>(hhi, hlo, w2lhi, w2llo, A, NNODES, HID, HID);
    k_hgemm<<<gg, T, 2 * STG_ALL>>>(hhi, hlo, w2rhi, w2rlo, B, NNODES, HID, HID);
    k_gat640<<<nwN, T>>>(A, B, rowptr, csr_src, a2, b2, hhi, hlo);

    // ---- Layer 3: GCN + relu + fused pooling ----
    k_hgemm<<<gg, T, 2 * STG_ALL>>>(hhi, hlo, wghi, wglo, A, NNODES, HID, HID);
    k_fill_i<<<ghb, T>>>(gmax, 0, NGRAPH * HID);         // relu => values >= 0
    k_fill_f<<<ghb, T>>>(gsum, 0.f, NGRAPH * HID);
    k_fill_f<<<(NGRAPH + T - 1) / T, T>>>(cnt, 0.f, NGRAPH);
    k_cnt<<<nb, T>>>(batch, cnt);
    k_gcn_node<<<nwN, T>>>(A, rowptr, csr_src, dinv, bg, batch, gmax, gsum);
    k_final<<<ghb, T>>>(gmax, gsum, cnt, out);
}

// round 13
// speedup vs baseline: 1.3947x; 1.3947x over previous
#include <cuda_runtime.h>
#include <cuda_bf16.h>
#include <cstdint>

#define NNODES 50000
#define NEDGES 150000
#define EPLUS  (NEDGES + NNODES)   // edges + self loops = 200000
#define NGRAPH 1024
#define INDIM  78
#define KP1    128                 // layer-1 K padded to 128
#define HID    640
#define HEADS  10
#define C1     64
#define NEGSLOPE 0.2f

// ---------------- scratch (static __device__ — no allocations allowed) -----
__device__ __align__(128) float g_bufA[(size_t)NNODES * HID];
__device__ __align__(128) float g_bufB[(size_t)NNODES * HID];
__device__ __align__(128) float g_logits[(size_t)EPLUS * HEADS];
__device__ float g_dinv[NNODES];
__device__ int   g_rowptr[NNODES + 1];
__device__ int   g_cntbuf[NNODES];
__device__ int   g_csr_src[EPLUS];
__device__ int   g_csr_eid[EPLUS];
__device__ int   g_gmax[NGRAPH * HID];
__device__ float g_gsum[NGRAPH * HID];
__device__ float g_cnt [NGRAPH];
// bf16 split buffers
__device__ __align__(128) __nv_bfloat16 g_xhi[(size_t)NNODES * KP1];
__device__ __align__(128) __nv_bfloat16 g_xlo[(size_t)NNODES * KP1];
__device__ __align__(128) __nv_bfloat16 g_hhi[(size_t)NNODES * HID];
__device__ __align__(128) __nv_bfloat16 g_hlo[(size_t)NNODES * HID];
__device__ __align__(128) __nv_bfloat16 g_w1lhi[HID * KP1], g_w1llo[HID * KP1];
__device__ __align__(128) __nv_bfloat16 g_w1rhi[HID * KP1], g_w1rlo[HID * KP1];
__device__ __align__(128) __nv_bfloat16 g_w2lhi[HID * HID], g_w2llo[HID * HID];
__device__ __align__(128) __nv_bfloat16 g_w2rhi[HID * HID], g_w2rlo[HID * HID];
__device__ __align__(128) __nv_bfloat16 g_wghi [HID * HID], g_wglo [HID * HID];

// ---------------- helpers --------------------------------------------------
__device__ __forceinline__ uint32_t smem_u32(const void* p) {
    return (uint32_t)__cvta_generic_to_shared(p);
}
#define LDSM4(r0, r1, r2, r3, addr) \
    asm volatile("ldmatrix.sync.aligned.m8n8.x4.shared.b16 {%0,%1,%2,%3}, [%4];" \
                 : "=r"(r0), "=r"(r1), "=r"(r2), "=r"(r3) : "r"(addr))
#define MMA16816(c, a0, a1, a2, a3, b0, b1) \
    asm volatile("mma.sync.aligned.m16n8k16.row.col.f32.bf16.bf16.f32 " \
                 "{%0,%1,%2,%3}, {%4,%5,%6,%7}, {%8,%9}, {%0,%1,%2,%3};" \
                 : "+f"((c)[0]), "+f"((c)[1]), "+f"((c)[2]), "+f"((c)[3]) \
                 : "r"(a0), "r"(a1), "r"(a2), "r"(a3), "r"(b0), "r"(b1))
__device__ __forceinline__ void cpasync16(uint32_t dst, const void* src, int sz) {
    asm volatile("cp.async.cg.shared.global [%0], [%1], 16, %2;"
                 :: "r"(dst), "l"(src), "r"(sz));
}
#define CP_COMMIT asm volatile("cp.async.commit_group;")
#define CP_WAIT1  asm volatile("cp.async.wait_group 1;")
#define CP_WAIT0  asm volatile("cp.async.wait_group 0;")

// ---------------- fills ----------------------------------------------------
__global__ void k_fill_f(float* p, float v, int n) {
    int i = blockIdx.x * blockDim.x + threadIdx.x;
    if (i < n) p[i] = v;
}
__global__ void k_fill_i(int* p, int v, int n) {
    int i = blockIdx.x * blockDim.x + threadIdx.x;
    if (i < n) p[i] = v;
}

// ---------------- CSR build ------------------------------------------------
__global__ void k_count(const int* __restrict__ ei, int* __restrict__ cnt) {
    int e = blockIdx.x * blockDim.x + threadIdx.x;
    if (e >= EPLUS) return;
    int d = (e < NEDGES) ? ei[NEDGES + e] : e - NEDGES;
    atomicAdd(&cnt[d], 1);
}
__global__ void k_scan(const int* __restrict__ cnt, int* __restrict__ rowptr) {
    __shared__ int sh[1024];
    __shared__ int carry;
    if (threadIdx.x == 0) carry = 0;
    __syncthreads();
    for (int base = 0; base < NNODES; base += 1024) {
        int i = base + threadIdx.x;
        int v = (i < NNODES) ? cnt[i] : 0;
        sh[threadIdx.x] = v;
        __syncthreads();
        for (int off = 1; off < 1024; off <<= 1) {
            int t = (threadIdx.x >= off) ? sh[threadIdx.x - off] : 0;
            __syncthreads();
            sh[threadIdx.x] += t;
            __syncthreads();
        }
        if (i < NNODES) rowptr[i] = carry + sh[threadIdx.x] - v;
        __syncthreads();
        if (threadIdx.x == 1023) carry += sh[1023];
        __syncthreads();
    }
    if (threadIdx.x == 0) rowptr[NNODES] = EPLUS;
}
__global__ void k_scatter(const int* __restrict__ ei, const int* __restrict__ rowptr,
                          int* __restrict__ fill, int* __restrict__ csr_src,
                          int* __restrict__ csr_eid) {
    int e = blockIdx.x * blockDim.x + threadIdx.x;
    if (e >= EPLUS) return;
    int s, d;
    if (e < NEDGES) { s = ei[e]; d = ei[NEDGES + e]; }
    else            { s = d = e - NEDGES; }
    int pos = rowptr[d] + atomicAdd(&fill[d], 1);
    csr_src[pos] = s;
    csr_eid[pos] = e;
}
__global__ void k_dinv(const int* __restrict__ rowptr, float* __restrict__ dinv) {
    int n = blockIdx.x * blockDim.x + threadIdx.x;
    if (n >= NNODES) return;
    dinv[n] = rsqrtf((float)(rowptr[n + 1] - rowptr[n]));   // >=1 (self loop)
}

// ---------------- bf16 hi/lo split prep ------------------------------------
__global__ void k_split(const float* __restrict__ src,
                        __nv_bfloat16* __restrict__ hi, __nv_bfloat16* __restrict__ lo,
                        int M, int K, int Kp)
{
    int idx = blockIdx.x * blockDim.x + threadIdx.x;
    if (idx >= M * Kp) return;
    int r = idx / Kp, k = idx - r * Kp;
    float v = (k < K) ? src[(size_t)r * K + k] : 0.f;
    __nv_bfloat16 h = __float2bfloat16(v);
    hi[idx] = h;
    lo[idx] = __float2bfloat16(v - __bfloat162float(h));
}
__global__ void k_splitT(const float* __restrict__ W,
                         __nv_bfloat16* __restrict__ hi, __nv_bfloat16* __restrict__ lo,
                         int K, int N, int Kp)
{
    int idx = blockIdx.x * blockDim.x + threadIdx.x;
    if (idx >= N * Kp) return;
    int n = idx / Kp, k = idx - n * Kp;
    float v = (k < K) ? W[(size_t)k * N + n] : 0.f;
    __nv_bfloat16 h = __float2bfloat16(v);
    hi[idx] = h;
    lo[idx] = __float2bfloat16(v - __bfloat162float(h));
}

// ---------------- split-bf16 HMMA GEMM, cp.async double buffer -------------
#define STG_T   10240               // bytes per tensor per stage (128*80)
#define STG_ALL 40960               // bytes per stage

__global__ __launch_bounds__(256, 2)
void k_hgemm(const __nv_bfloat16* __restrict__ Ahi, const __nv_bfloat16* __restrict__ Alo,
             const __nv_bfloat16* __restrict__ Bhi, const __nv_bfloat16* __restrict__ Blo,
             float* __restrict__ C, int M, int N, int K)
{
    extern __shared__ __align__(128) char smem[];
    const uint32_t sb = smem_u32(smem);
    const int tid = threadIdx.x, lane = tid & 31, wid = tid >> 5;
    const int wm = wid & 3, wn = wid >> 2;
    const int bm = blockIdx.y * 128, bn = blockIdx.x * 128;

    float c[2][8][4];
    #pragma unroll
    for (int i = 0; i < 2; i++)
        #pragma unroll
        for (int j = 0; j < 8; j++)
            #pragma unroll
            for (int q = 0; q < 4; q++) c[i][j][q] = 0.f;

    const int row = tid >> 1, half = tid & 1;
    const bool va = (bm + row) < M;
    const int szA = va ? 16 : 0;
    const char* gAh = (const char*)(Ahi + (size_t)(bm + row) * K) + half * 32;
    const char* gAl = (const char*)(Alo + (size_t)(bm + row) * K) + half * 32;
    const char* gBh = (const char*)(Bhi + (size_t)(bn + row) * K) + half * 32;
    const char* gBl = (const char*)(Blo + (size_t)(bn + row) * K) + half * 32;
    const uint32_t dOff = (uint32_t)(row * 80 + half * 32);

#define LOAD_STAGE(s, k0) do {                                              \
        uint32_t b_ = sb + (uint32_t)((s) & 1) * STG_ALL;                   \
        size_t kb_ = (size_t)(k0) * 2;                                      \
        cpasync16(b_ + 0 * STG_T + dOff,      gAh + kb_,      szA);         \
        cpasync16(b_ + 0 * STG_T + dOff + 16, gAh + kb_ + 16, szA);         \
        cpasync16(b_ + 1 * STG_T + dOff,      gAl + kb_,      szA);         \
        cpasync16(b_ + 1 * STG_T + dOff + 16, gAl + kb_ + 16, szA);         \
        cpasync16(b_ + 2 * STG_T + dOff,      gBh + kb_,      16);          \
        cpasync16(b_ + 2 * STG_T + dOff + 16, gBh + kb_ + 16, 16);          \
        cpasync16(b_ + 3 * STG_T + dOff,      gBl + kb_,      16);          \
        cpasync16(b_ + 3 * STG_T + dOff + 16, gBl + kb_ + 16, 16);          \
    } while (0)

    const uint32_t a_mr = (lane & 7) + ((lane >> 3) & 1) * 8;
    const uint32_t a_kc = (lane >> 4) * 8;
    const uint32_t b_nr = ((lane >> 4) & 1) * 8 + (lane & 7);
    const uint32_t b_kc = ((lane >> 3) & 1) * 8;

    const int nst = K >> 5;
    LOAD_STAGE(0, 0);
    CP_COMMIT;
    for (int s = 0; s < nst; s++) {
        if (s + 1 < nst) { LOAD_STAGE(s + 1, (s + 1) << 5); CP_COMMIT; CP_WAIT1; }
        else             { CP_WAIT0; }
        __syncthreads();

        uint32_t base = sb + (uint32_t)(s & 1) * STG_ALL;
        #pragma unroll
        for (int ksub = 0; ksub < 2; ksub++) {
            uint32_t ko = ksub * 32;
            uint32_t ah[2][4], al[2][4];
            #pragma unroll
            for (int mt = 0; mt < 2; mt++) {
                uint32_t aaddr = (uint32_t)((wm * 32 + mt * 16 + a_mr) * 80) + ko + a_kc * 2;
                LDSM4(ah[mt][0], ah[mt][1], ah[mt][2], ah[mt][3], base + 0 * STG_T + aaddr);
                LDSM4(al[mt][0], al[mt][1], al[mt][2], al[mt][3], base + 1 * STG_T + aaddr);
            }
            #pragma unroll
            for (int bg = 0; bg < 4; bg++) {
                uint32_t baddr = (uint32_t)((wn * 64 + bg * 16 + b_nr) * 80) + ko + b_kc * 2;
                uint32_t bh0, bh1, bh2, bh3, bl0, bl1, bl2, bl3;
                LDSM4(bh0, bh1, bh2, bh3, base + 2 * STG_T + baddr);
                LDSM4(bl0, bl1, bl2, bl3, base + 3 * STG_T + baddr);
                #pragma unroll
                for (int mt = 0; mt < 2; mt++) {
                    float* c0 = c[mt][bg * 2];
                    float* c1 = c[mt][bg * 2 + 1];
                    MMA16816(c0, ah[mt][0], ah[mt][1], ah[mt][2], ah[mt][3], bh0, bh1);
                    MMA16816(c0, ah[mt][0], ah[mt][1], ah[mt][2], ah[mt][3], bl0, bl1);
                    MMA16816(c0, al[mt][0], al[mt][1], al[mt][2], al[mt][3], bh0, bh1);
                    MMA16816(c1, ah[mt][0], ah[mt][1], ah[mt][2], ah[mt][3], bh2, bh3);
                    MMA16816(c1, ah[mt][0], ah[mt][1], ah[mt][2], ah[mt][3], bl2, bl3);
                    MMA16816(c1, al[mt][0], al[mt][1], al[mt][2], al[mt][3], bh2, bh3);
                }
            }
        }
        __syncthreads();
    }
#undef LOAD_STAGE

    const int rbase = bm + wm * 32 + (lane >> 2);
    const int cbase = bn + wn * 64 + (lane & 3) * 2;
    #pragma unroll
    for (int mt = 0; mt < 2; mt++) {
        #pragma unroll
        for (int nt = 0; nt < 8; nt++) {
            int rr = rbase + mt * 16;
            int cc = cbase + nt * 8;
            if (rr < M)
                *(float2*)&C[(size_t)rr * N + cc] = make_float2(c[mt][nt][0], c[mt][nt][1]);
            if (rr + 8 < M)
                *(float2*)&C[(size_t)(rr + 8) * N + cc] = make_float2(c[mt][nt][2], c[mt][nt][3]);
        }
    }
}

// ---------------- layer-1 edge logits: H=10, two heads per pass ------------
// lanes 0-15 -> head 2j, lanes 16-31 -> head 2j+1; full-warp loads, rows
// read exactly once; 4-deep intra-16-lane reduction.
__global__ void k_edge_logits10(const float* __restrict__ xl,
                                const float* __restrict__ xr,
                                const int* __restrict__ ei,
                                const float* __restrict__ att,
                                float* __restrict__ logits)
{
    int e = (blockIdx.x * blockDim.x + threadIdx.x) >> 5;
    int lane = threadIdx.x & 31;
    if (e >= EPLUS) return;
    int s, d;
    if (e < NEDGES) { s = ei[e]; d = ei[NEDGES + e]; }
    else            { s = d = e - NEDGES; }
    const float4* pl = (const float4*)(xl + (size_t)s * HID);
    const float4* pr = (const float4*)(xr + (size_t)d * HID);
    const float4* pa = (const float4*)att;
    int sub = lane >> 4;            // which head of the pair
    int q   = lane & 15;            // float4 index within head (Q=16)
    #pragma unroll
    for (int hp = 0; hp < 5; hp++) {
        int h = 2 * hp + sub;
        int idx = h * 16 + q;
        float4 l4 = pl[idx];
        float4 r4 = pr[idx];
        float4 a4 = pa[idx];
        float v, sum = 0.f;
        v = l4.x + r4.x; v = v > 0.f ? v : NEGSLOPE * v; sum += v * a4.x;
        v = l4.y + r4.y; v = v > 0.f ? v : NEGSLOPE * v; sum += v * a4.y;
        v = l4.z + r4.z; v = v > 0.f ? v : NEGSLOPE * v; sum += v * a4.z;
        v = l4.w + r4.w; v = v > 0.f ? v : NEGSLOPE * v; sum += v * a4.w;
        #pragma unroll
        for (int o = 8; o > 0; o >>= 1)
            sum += __shfl_xor_sync(0xffffffffu, sum, o);
        if (q == 0) logits[(size_t)e * HEADS + h] = sum;
    }
}

// ---------------- layer-2 edge logits: H=1, Ch=640 (warp per edge) ---------
__global__ void k_edge_logits640(const float* __restrict__ xl,
                                 const float* __restrict__ xr,
                                 const int* __restrict__ ei,
                                 const float* __restrict__ att,
                                 float* __restrict__ logits)
{
    int e = (blockIdx.x * blockDim.x + threadIdx.x) >> 5;
    int lane = threadIdx.x & 31;
    if (e >= EPLUS) return;
    int s, d;
    if (e < NEDGES) { s = ei[e]; d = ei[NEDGES + e]; }
    else            { s = d = e - NEDGES; }
    const float4* pl = (const float4*)(xl + (size_t)s * HID);
    const float4* pr = (const float4*)(xr + (size_t)d * HID);
    const float4* pa = (const float4*)att;
    float sum = 0.f;
    #pragma unroll
    for (int j = 0; j < 5; j++) {
        int q = j * 32 + lane;
        float4 l4 = pl[q];
        float4 r4 = pr[q];
        float4 a4 = pa[q];
        float v;
        v = l4.x + r4.x; v = v > 0.f ? v : NEGSLOPE * v; sum += v * a4.x;
        v = l4.y + r4.y; v = v > 0.f ? v : NEGSLOPE * v; sum += v * a4.y;
        v = l4.z + r4.z; v = v > 0.f ? v : NEGSLOPE * v; sum += v * a4.z;
        v = l4.w + r4.w; v = v > 0.f ? v : NEGSLOPE * v; sum += v * a4.w;
    }
    #pragma unroll
    for (int o = 16; o > 0; o >>= 1)
        sum += __shfl_xor_sync(0xffffffffu, sum, o);
    if (lane == 0) logits[e] = sum;
}

// ---------------- GATv2 node aggregate, H=10 Ch=64 (warp per node,head) ----
__global__ void k_gat_node64(const float* __restrict__ xl,
                             const int* __restrict__ rowptr,
                             const int* __restrict__ csr_src,
                             const int* __restrict__ csr_eid,
                             const float* __restrict__ logits,
                             const float* __restrict__ bias,
                             __nv_bfloat16* __restrict__ ohi,
                             __nv_bfloat16* __restrict__ olo)
{
    int gw = (blockIdx.x * blockDim.x + threadIdx.x) >> 5;
    int lane = threadIdx.x & 31;
    if (gw >= NNODES * HEADS) return;
    int n = gw / HEADS, h = gw - n * HEADS;
    int r0 = rowptr[n], r1 = rowptr[n + 1];

    float m = -3.4e38f;
    for (int i = r0 + lane; i < r1; i += 32)
        m = fmaxf(m, logits[(size_t)csr_eid[i] * HEADS + h]);
    #pragma unroll
    for (int o = 16; o > 0; o >>= 1)
        m = fmaxf(m, __shfl_xor_sync(0xffffffffu, m, o));

    float den = 0.f, a0 = 0.f, a1 = 0.f;
    int cbase = h * C1 + lane * 2;
    for (int i = r0; i < r1; i++) {
        int s = csr_src[i];
        float ex = expf(logits[(size_t)csr_eid[i] * HEADS + h] - m);
        den += ex;
        float2 v = *(const float2*)&xl[(size_t)s * HID + cbase];
        a0 += ex * v.x;
        a1 += ex * v.y;
    }
    float o0 = a0 / den + bias[cbase];
    float o1 = a1 / den + bias[cbase + 1];
    o0 = o0 > 0.f ? o0 : expm1f(o0);
    o1 = o1 > 0.f ? o1 : expm1f(o1);
    __nv_bfloat16 h0 = __float2bfloat16(o0), h1 = __float2bfloat16(o1);
    __nv_bfloat162 hp; hp.x = h0; hp.y = h1;
    __nv_bfloat162 lp;
    lp.x = __float2bfloat16(o0 - __bfloat162float(h0));
    lp.y = __float2bfloat16(o1 - __bfloat162float(h1));
    *(__nv_bfloat162*)&ohi[(size_t)n * HID + cbase] = hp;
    *(__nv_bfloat162*)&olo[(size_t)n * HID + cbase] = lp;
}

// ---------------- GATv2 node aggregate, H=1 Ch=640 (warp per node) ---------
__global__ void k_gat_node640(const float* __restrict__ xl,
                              const int* __restrict__ rowptr,
                              const int* __restrict__ csr_src,
                              const int* __restrict__ csr_eid,
                              const float* __restrict__ logits,
                              const float* __restrict__ bias,
                              __nv_bfloat16* __restrict__ ohi,
                              __nv_bfloat16* __restrict__ olo)
{
    int n = (blockIdx.x * blockDim.x + threadIdx.x) >> 5;
    int lane = threadIdx.x & 31;
    if (n >= NNODES) return;
    int r0 = rowptr[n], r1 = rowptr[n + 1];

    float m = -3.4e38f;
    for (int i = r0 + lane; i < r1; i += 32)
        m = fmaxf(m, logits[csr_eid[i]]);
    #pragma unroll
    for (int o = 16; o > 0; o >>= 1)
        m = fmaxf(m, __shfl_xor_sync(0xffffffffu, m, o));

    float den = 0.f;
    float acc[5][4];
    #pragma unroll
    for (int j = 0; j < 5; j++)
        #pragma unroll
        for (int q = 0; q < 4; q++) acc[j][q] = 0.f;

    for (int i = r0; i < r1; i++) {
        int s = csr_src[i];
        float ex = expf(logits[csr_eid[i]] - m);
        den += ex;
        const float4* ps = (const float4*)(xl + (size_t)s * HID);
        #pragma unroll
        for (int j = 0; j < 5; j++) {
            float4 v = ps[j * 32 + lane];
            acc[j][0] += ex * v.x;
            acc[j][1] += ex * v.y;
            acc[j][2] += ex * v.z;
            acc[j][3] += ex * v.w;
        }
    }
    float inv = 1.f / den;
    #pragma unroll
    for (int j = 0; j < 5; j++) {
        int cb = (j * 32 + lane) * 4;
        float o0 = acc[j][0] * inv + bias[cb];
        float o1 = acc[j][1] * inv + bias[cb + 1];
        float o2 = acc[j][2] * inv + bias[cb + 2];
        float o3 = acc[j][3] * inv + bias[cb + 3];
        __nv_bfloat16 h0 = __float2bfloat16(o0), h1 = __float2bfloat16(o1);
        __nv_bfloat16 h2 = __float2bfloat16(o2), h3 = __float2bfloat16(o3);
        __nv_bfloat162 hp0; hp0.x = h0; hp0.y = h1;
        __nv_bfloat162 hp1; hp1.x = h2; hp1.y = h3;
        __nv_bfloat162 lp0, lp1;
        lp0.x = __float2bfloat16(o0 - __bfloat162float(h0));
        lp0.y = __float2bfloat16(o1 - __bfloat162float(h1));
        lp1.x = __float2bfloat16(o2 - __bfloat162float(h2));
        lp1.y = __float2bfloat16(o3 - __bfloat162float(h3));
        *(__nv_bfloat162*)&ohi[(size_t)n * HID + cb]     = hp0;
        *(__nv_bfloat162*)&ohi[(size_t)n * HID + cb + 2] = hp1;
        *(__nv_bfloat162*)&olo[(size_t)n * HID + cb]     = lp0;
        *(__nv_bfloat162*)&olo[(size_t)n * HID + cb + 2] = lp1;
    }
}

// ---------------- GCN node aggregate + relu + fused pooling ----------------
__global__ void k_gcn_node(const float* __restrict__ xw,
                           const int* __restrict__ rowptr,
                           const int* __restrict__ csr_src,
                           const float* __restrict__ dinv,
                           const float* __restrict__ bg,
                           const int* __restrict__ batch,
                           int* __restrict__ gmax, float* __restrict__ gsum)
{
    int n = (blockIdx.x * blockDim.x + threadIdx.x) >> 5;
    int lane = threadIdx.x & 31;
    if (n >= NNODES) return;
    int r0 = rowptr[n], r1 = rowptr[n + 1];
    float dv = dinv[n];

    float acc[5][4];
    #pragma unroll
    for (int j = 0; j < 5; j++)
        #pragma unroll
        for (int q = 0; q < 4; q++) acc[j][q] = 0.f;

    for (int i = r0; i < r1; i++) {
        int s = csr_src[i];
        float nrm = dinv[s] * dv;
        const float4* ps = (const float4*)(xw + (size_t)s * HID);
        #pragma unroll
        for (int j = 0; j < 5; j++) {
            float4 v = ps[j * 32 + lane];
            acc[j][0] += nrm * v.x;
            acc[j][1] += nrm * v.y;
            acc[j][2] += nrm * v.z;
            acc[j][3] += nrm * v.w;
        }
    }
    int g = batch[n];
    #pragma unroll
    for (int j = 0; j < 5; j++) {
        int cb = (j * 32 + lane) * 4;
        #pragma unroll
        for (int q = 0; q < 4; q++) {
            float o = fmaxf(acc[j][q] + bg[cb + q], 0.f);
            atomicMax(&gmax[g * HID + cb + q], __float_as_int(o));
            atomicAdd(&gsum[g * HID + cb + q], o);
        }
    }
}

// ---------------- pooling tail ---------------------------------------------
__global__ void k_cnt(const int* __restrict__ batch, float* __restrict__ cnt) {
    int n = blockIdx.x * blockDim.x + threadIdx.x;
    if (n >= NNODES) return;
    atomicAdd(&cnt[batch[n]], 1.f);
}
__global__ void k_final(const int* __restrict__ gmax, const float* __restrict__ gsum,
                        const float* __restrict__ cnt, float* __restrict__ out)
{
    int idx = blockIdx.x * blockDim.x + threadIdx.x;
    if (idx >= NGRAPH * HID) return;
    int g = idx / HID, c = idx % HID;
    out[(size_t)g * (2 * HID) + c]       = __int_as_float(gmax[idx]);
    out[(size_t)g * (2 * HID) + HID + c] = gsum[idx] / fmaxf(cnt[g], 1.f);
}

// ---------------- launch ---------------------------------------------------
extern "C" void kernel_launch(void* const* d_in, const int* in_sizes, int n_in,
                              void* d_out, int out_size)
{
    const float* x     = (const float*)d_in[0];
    const int*   ei    = (const int*)d_in[1];
    const int*   batch = (const int*)d_in[2];
    const float* Wl1 = (const float*)d_in[3];
    const float* Wr1 = (const float*)d_in[4];
    const float* a1  = (const float*)d_in[5];
    const float* b1  = (const float*)d_in[6];
    const float* Wl2 = (const float*)d_in[7];
    const float* Wr2 = (const float*)d_in[8];
    const float* a2  = (const float*)d_in[9];
    const float* b2  = (const float*)d_in[10];
    const float* Wg  = (const float*)d_in[11];
    const float* bg  = (const float*)d_in[12];
    float* out = (float*)d_out;

    float *A, *B, *logits, *dinv, *gsum, *cnt;
    int *rowptr, *cntbuf, *csr_src, *csr_eid, *gmax;
    __nv_bfloat16 *xhi, *xlo, *hhi, *hlo;
    __nv_bfloat16 *w1lhi, *w1llo, *w1rhi, *w1rlo;
    __nv_bfloat16 *w2lhi, *w2llo, *w2rhi, *w2rlo, *wghi, *wglo;
    cudaGetSymbolAddress((void**)&A,       g_bufA);
    cudaGetSymbolAddress((void**)&B,       g_bufB);
    cudaGetSymbolAddress((void**)&logits,  g_logits);
    cudaGetSymbolAddress((void**)&dinv,    g_dinv);
    cudaGetSymbolAddress((void**)&rowptr,  g_rowptr);
    cudaGetSymbolAddress((void**)&cntbuf,  g_cntbuf);
    cudaGetSymbolAddress((void**)&csr_src, g_csr_src);
    cudaGetSymbolAddress((void**)&csr_eid, g_csr_eid);
    cudaGetSymbolAddress((void**)&gmax,    g_gmax);
    cudaGetSymbolAddress((void**)&gsum,    g_gsum);
    cudaGetSymbolAddress((void**)&cnt,     g_cnt);
    cudaGetSymbolAddress((void**)&xhi,     g_xhi);
    cudaGetSymbolAddress((void**)&xlo,     g_xlo);
    cudaGetSymbolAddress((void**)&hhi,     g_hhi);
    cudaGetSymbolAddress((void**)&hlo,     g_hlo);
    cudaGetSymbolAddress((void**)&w1lhi,   g_w1lhi);
    cudaGetSymbolAddress((void**)&w1llo,   g_w1llo);
    cudaGetSymbolAddress((void**)&w1rhi,   g_w1rhi);
    cudaGetSymbolAddress((void**)&w1rlo,   g_w1rlo);
    cudaGetSymbolAddress((void**)&w2lhi,   g_w2lhi);
    cudaGetSymbolAddress((void**)&w2llo,   g_w2llo);
    cudaGetSymbolAddress((void**)&w2rhi,   g_w2rhi);
    cudaGetSymbolAddress((void**)&w2rlo,   g_w2rlo);
    cudaGetSymbolAddress((void**)&wghi,    g_wghi);
    cudaGetSymbolAddress((void**)&wglo,    g_wglo);

    static bool attr_set = false;
    if (!attr_set) {
        cudaFuncSetAttribute(k_hgemm, cudaFuncAttributeMaxDynamicSharedMemorySize, 2 * STG_ALL);
        attr_set = true;
    }

    const int T = 256;
    dim3 gg(HID / 128, (NNODES + 127) / 128);            // (5, 391)
    int eb   = (EPLUS * 32 + T - 1) / T;                 // warp per edge
    int nb   = (NNODES + T - 1) / T;
    int epb  = (EPLUS + T - 1) / T;
    int ghb  = (NGRAPH * HID + T - 1) / T;
    int xsb  = (NNODES * KP1 + T - 1) / T;
    int w1b  = (HID * KP1 + T - 1) / T;
    int w2b  = (HID * HID + T - 1) / T;
    int nw64 = (NNODES * HEADS * 32 + T - 1) / T;        // warp per (node,head)
    int nwN  = (NNODES * 32 + T - 1) / T;                // warp per node

    // ---- CSR build (dst-sorted, incl self loops) ----
    k_fill_i<<<nb, T>>>(cntbuf, 0, NNODES);
    k_count<<<epb, T>>>(ei, cntbuf);
    k_scan<<<1, 1024>>>(cntbuf, rowptr);
    k_fill_i<<<nb, T>>>(cntbuf, 0, NNODES);
    k_scatter<<<epb, T>>>(ei, rowptr, cntbuf, csr_src, csr_eid);
    k_dinv<<<nb, T>>>(rowptr, dinv);

    // ---- bf16 hi/lo splits (weights + x) ----
    k_split <<<xsb, T>>>(x, xhi, xlo, NNODES, INDIM, KP1);
    k_splitT<<<w1b, T>>>(Wl1, w1lhi, w1llo, INDIM, HID, KP1);
    k_splitT<<<w1b, T>>>(Wr1, w1rhi, w1rlo, INDIM, HID, KP1);
    k_splitT<<<w2b, T>>>(Wl2, w2lhi, w2llo, HID, HID, HID);
    k_splitT<<<w2b, T>>>(Wr2, w2rhi, w2rlo, HID, HID, HID);
    k_splitT<<<w2b, T>>>(Wg,  wghi,  wglo,  HID, HID, HID);

    // ---- Layer 1: GATv2 (heads=10, C=64) ----
    k_hgemm<<<gg, T, 2 * STG_ALL>>>(xhi, xlo, w1lhi, w1llo, A, NNODES, HID, KP1);
    k_hgemm<<<gg, T, 2 * STG_ALL>>>(xhi, xlo, w1rhi, w1rlo, B, NNODES, HID, KP1);
    k_edge_logits10<<<eb, T>>>(A, B, ei, a1, logits);
    k_gat_node64<<<nw64, T>>>(A, rowptr, csr_src, csr_eid, logits, b1, hhi, hlo);

    // ---- Layer 2: GATv2 (heads=1, C=640) ----
    k_hgemm<<<gg, T, 2 * STG_ALL>>>(hhi, hlo, w2lhi, w2llo, A, NNODES, HID, HID);
    k_hgemm<<<gg, T, 2 * STG_ALL>>>(hhi, hlo, w2rhi, w2rlo, B, NNODES, HID, HID);
    k_edge_logits640<<<eb, T>>>(A, B, ei, a2, logits);
    k_gat_node640<<<nwN, T>>>(A, rowptr, csr_src, csr_eid, logits, b2, hhi, hlo);

    // ---- Layer 3: GCN + relu + fused pooling ----
    k_hgemm<<<gg, T, 2 * STG_ALL>>>(hhi, hlo, wghi, wglo, A, NNODES, HID, HID);
    k_fill_i<<<ghb, T>>>(gmax, 0, NGRAPH * HID);         // relu => values >= 0
    k_fill_f<<<ghb, T>>>(gsum, 0.f, NGRAPH * HID);
    k_fill_f<<<(NGRAPH + T - 1) / T, T>>>(cnt, 0.f, NGRAPH);
    k_cnt<<<nb, T>>>(batch, cnt);
    k_gcn_node<<<nwN, T>>>(A, rowptr, csr_src, dinv, bg, batch, gmax, gsum);
    k_final<<<ghb, T>>>(gmax, gsum, cnt, out);
}

// round 14
// speedup vs baseline: 1.4587x; 1.0458x over previous
#include <cuda_runtime.h>
#include <cuda_bf16.h>
#include <cstdint>

#define NNODES 50000
#define NEDGES 150000
#define EPLUS  (NEDGES + NNODES)   // edges + self loops = 200000
#define NGRAPH 1024
#define INDIM  78
#define KP1    128                 // layer-1 K padded to 128
#define HID    640
#define HEADS  10
#define C1     64
#define NEGSLOPE 0.2f

// ---------------- scratch (static __device__ — no allocations allowed) -----
__device__ __align__(128) float g_bufA[(size_t)NNODES * HID];
__device__ __align__(128) float g_bufB[(size_t)NNODES * HID];
__device__ __align__(128) float g_logits[(size_t)EPLUS * HEADS];  // CSR order
__device__ float g_dinv[NNODES];
__device__ int   g_rowptr[NNODES + 1];
__device__ int   g_cntbuf[NNODES];
__device__ int   g_csr_src[EPLUS];
__device__ int   g_gmax[NGRAPH * HID];
__device__ float g_gsum[NGRAPH * HID];
__device__ float g_cnt [NGRAPH];
// bf16 split buffers
__device__ __align__(128) __nv_bfloat16 g_xhi[(size_t)NNODES * KP1];
__device__ __align__(128) __nv_bfloat16 g_xlo[(size_t)NNODES * KP1];
__device__ __align__(128) __nv_bfloat16 g_hhi[(size_t)NNODES * HID];
__device__ __align__(128) __nv_bfloat16 g_hlo[(size_t)NNODES * HID];
__device__ __align__(128) __nv_bfloat16 g_w1lhi[HID * KP1], g_w1llo[HID * KP1];
__device__ __align__(128) __nv_bfloat16 g_w1rhi[HID * KP1], g_w1rlo[HID * KP1];
__device__ __align__(128) __nv_bfloat16 g_w2lhi[HID * HID], g_w2llo[HID * HID];
__device__ __align__(128) __nv_bfloat16 g_w2rhi[HID * HID], g_w2rlo[HID * HID];
__device__ __align__(128) __nv_bfloat16 g_wghi [HID * HID], g_wglo [HID * HID];

// ---------------- helpers --------------------------------------------------
__device__ __forceinline__ uint32_t smem_u32(const void* p) {
    return (uint32_t)__cvta_generic_to_shared(p);
}
#define LDSM4(r0, r1, r2, r3, addr) \
    asm volatile("ldmatrix.sync.aligned.m8n8.x4.shared.b16 {%0,%1,%2,%3}, [%4];" \
                 : "=r"(r0), "=r"(r1), "=r"(r2), "=r"(r3) : "r"(addr))
#define MMA16816(c, a0, a1, a2, a3, b0, b1) \
    asm volatile("mma.sync.aligned.m16n8k16.row.col.f32.bf16.bf16.f32 " \
                 "{%0,%1,%2,%3}, {%4,%5,%6,%7}, {%8,%9}, {%0,%1,%2,%3};" \
                 : "+f"((c)[0]), "+f"((c)[1]), "+f"((c)[2]), "+f"((c)[3]) \
                 : "r"(a0), "r"(a1), "r"(a2), "r"(a3), "r"(b0), "r"(b1))
__device__ __forceinline__ void cpasync16(uint32_t dst, const void* src, int sz) {
    asm volatile("cp.async.cg.shared.global [%0], [%1], 16, %2;"
                 :: "r"(dst), "l"(src), "r"(sz));
}
#define CP_COMMIT asm volatile("cp.async.commit_group;")
#define CP_WAIT1  asm volatile("cp.async.wait_group 1;")
#define CP_WAIT0  asm volatile("cp.async.wait_group 0;")

// ---------------- fills ----------------------------------------------------
__global__ void k_fill_i(int* p, int v, int n) {
    int i = blockIdx.x * blockDim.x + threadIdx.x;
    if (i < n) p[i] = v;
}
__global__ void k_pool_init(int* __restrict__ gmax, float* __restrict__ gsum,
                            float* __restrict__ cnt) {
    int i = blockIdx.x * blockDim.x + threadIdx.x;
    if (i < NGRAPH * HID) { gmax[i] = 0; gsum[i] = 0.f; }
    if (i < NGRAPH) cnt[i] = 0.f;
}

// ---------------- CSR build ------------------------------------------------
__global__ void k_count(const int* __restrict__ ei, int* __restrict__ cnt) {
    int e = blockIdx.x * blockDim.x + threadIdx.x;
    if (e >= EPLUS) return;
    int d = (e < NEDGES) ? ei[NEDGES + e] : e - NEDGES;
    atomicAdd(&cnt[d], 1);
}
__global__ void k_scan(const int* __restrict__ cnt, int* __restrict__ rowptr) {
    __shared__ int sh[1024];
    __shared__ int carry;
    if (threadIdx.x == 0) carry = 0;
    __syncthreads();
    for (int base = 0; base < NNODES; base += 1024) {
        int i = base + threadIdx.x;
        int v = (i < NNODES) ? cnt[i] : 0;
        sh[threadIdx.x] = v;
        __syncthreads();
        for (int off = 1; off < 1024; off <<= 1) {
            int t = (threadIdx.x >= off) ? sh[threadIdx.x - off] : 0;
            __syncthreads();
            sh[threadIdx.x] += t;
            __syncthreads();
        }
        if (i < NNODES) rowptr[i] = carry + sh[threadIdx.x] - v;
        __syncthreads();
        if (threadIdx.x == 1023) carry += sh[1023];
        __syncthreads();
    }
    if (threadIdx.x == 0) rowptr[NNODES] = EPLUS;
}
__global__ void k_scatter(const int* __restrict__ ei, const int* __restrict__ rowptr,
                          int* __restrict__ fill, int* __restrict__ csr_src) {
    int e = blockIdx.x * blockDim.x + threadIdx.x;
    if (e >= EPLUS) return;
    int s, d;
    if (e < NEDGES) { s = ei[e]; d = ei[NEDGES + e]; }
    else            { s = d = e - NEDGES; }
    int pos = rowptr[d] + atomicAdd(&fill[d], 1);
    csr_src[pos] = s;
}
__global__ void k_dinv(const int* __restrict__ rowptr, float* __restrict__ dinv) {
    int n = blockIdx.x * blockDim.x + threadIdx.x;
    if (n >= NNODES) return;
    dinv[n] = rsqrtf((float)(rowptr[n + 1] - rowptr[n]));   // >=1 (self loop)
}

// ---------------- bf16 hi/lo split prep ------------------------------------
__global__ void k_split(const float* __restrict__ src,
                        __nv_bfloat16* __restrict__ hi, __nv_bfloat16* __restrict__ lo,
                        int M, int K, int Kp)
{
    int idx = blockIdx.x * blockDim.x + threadIdx.x;
    if (idx >= M * Kp) return;
    int r = idx / Kp, k = idx - r * Kp;
    float v = (k < K) ? src[(size_t)r * K + k] : 0.f;
    __nv_bfloat16 h = __float2bfloat16(v);
    hi[idx] = h;
    lo[idx] = __float2bfloat16(v - __bfloat162float(h));
}
__global__ void k_splitT(const float* __restrict__ W,
                         __nv_bfloat16* __restrict__ hi, __nv_bfloat16* __restrict__ lo,
                         int K, int N, int Kp)
{
    int idx = blockIdx.x * blockDim.x + threadIdx.x;
    if (idx >= N * Kp) return;
    int n = idx / Kp, k = idx - n * Kp;
    float v = (k < K) ? W[(size_t)k * N + n] : 0.f;
    __nv_bfloat16 h = __float2bfloat16(v);
    hi[idx] = h;
    lo[idx] = __float2bfloat16(v - __bfloat162float(h));
}

// ---------------- split-bf16 HMMA GEMM, cp.async double buffer -------------
#define STG_T   10240               // bytes per tensor per stage (128*80)
#define STG_ALL 40960               // bytes per stage

__global__ __launch_bounds__(256, 2)
void k_hgemm(const __nv_bfloat16* __restrict__ Ahi, const __nv_bfloat16* __restrict__ Alo,
             const __nv_bfloat16* __restrict__ Bhi, const __nv_bfloat16* __restrict__ Blo,
             float* __restrict__ C, int M, int N, int K)
{
    extern __shared__ __align__(128) char smem[];
    const uint32_t sb = smem_u32(smem);
    const int tid = threadIdx.x, lane = tid & 31, wid = tid >> 5;
    const int wm = wid & 3, wn = wid >> 2;
    const int bm = blockIdx.y * 128, bn = blockIdx.x * 128;

    float c[2][8][4];
    #pragma unroll
    for (int i = 0; i < 2; i++)
        #pragma unroll
        for (int j = 0; j < 8; j++)
            #pragma unroll
            for (int q = 0; q < 4; q++) c[i][j][q] = 0.f;

    const int row = tid >> 1, half = tid & 1;
    const bool va = (bm + row) < M;
    const int szA = va ? 16 : 0;
    const char* gAh = (const char*)(Ahi + (size_t)(bm + row) * K) + half * 32;
    const char* gAl = (const char*)(Alo + (size_t)(bm + row) * K) + half * 32;
    const char* gBh = (const char*)(Bhi + (size_t)(bn + row) * K) + half * 32;
    const char* gBl = (const char*)(Blo + (size_t)(bn + row) * K) + half * 32;
    const uint32_t dOff = (uint32_t)(row * 80 + half * 32);

#define LOAD_STAGE(s, k0) do {                                              \
        uint32_t b_ = sb + (uint32_t)((s) & 1) * STG_ALL;                   \
        size_t kb_ = (size_t)(k0) * 2;                                      \
        cpasync16(b_ + 0 * STG_T + dOff,      gAh + kb_,      szA);         \
        cpasync16(b_ + 0 * STG_T + dOff + 16, gAh + kb_ + 16, szA);         \
        cpasync16(b_ + 1 * STG_T + dOff,      gAl + kb_,      szA);         \
        cpasync16(b_ + 1 * STG_T + dOff + 16, gAl + kb_ + 16, szA);         \
        cpasync16(b_ + 2 * STG_T + dOff,      gBh + kb_,      16);          \
        cpasync16(b_ + 2 * STG_T + dOff + 16, gBh + kb_ + 16, 16);          \
        cpasync16(b_ + 3 * STG_T + dOff,      gBl + kb_,      16);          \
        cpasync16(b_ + 3 * STG_T + dOff + 16, gBl + kb_ + 16, 16);          \
    } while (0)

    const uint32_t a_mr = (lane & 7) + ((lane >> 3) & 1) * 8;
    const uint32_t a_kc = (lane >> 4) * 8;
    const uint32_t b_nr = ((lane >> 4) & 1) * 8 + (lane & 7);
    const uint32_t b_kc = ((lane >> 3) & 1) * 8;

    const int nst = K >> 5;
    LOAD_STAGE(0, 0);
    CP_COMMIT;
    for (int s = 0; s < nst; s++) {
        if (s + 1 < nst) { LOAD_STAGE(s + 1, (s + 1) << 5); CP_COMMIT; CP_WAIT1; }
        else             { CP_WAIT0; }
        __syncthreads();

        uint32_t base = sb + (uint32_t)(s & 1) * STG_ALL;
        #pragma unroll
        for (int ksub = 0; ksub < 2; ksub++) {
            uint32_t ko = ksub * 32;
            uint32_t ah[2][4], al[2][4];
            #pragma unroll
            for (int mt = 0; mt < 2; mt++) {
                uint32_t aaddr = (uint32_t)((wm * 32 + mt * 16 + a_mr) * 80) + ko + a_kc * 2;
                LDSM4(ah[mt][0], ah[mt][1], ah[mt][2], ah[mt][3], base + 0 * STG_T + aaddr);
                LDSM4(al[mt][0], al[mt][1], al[mt][2], al[mt][3], base + 1 * STG_T + aaddr);
            }
            #pragma unroll
            for (int bg = 0; bg < 4; bg++) {
                uint32_t baddr = (uint32_t)((wn * 64 + bg * 16 + b_nr) * 80) + ko + b_kc * 2;
                uint32_t bh0, bh1, bh2, bh3, bl0, bl1, bl2, bl3;
                LDSM4(bh0, bh1, bh2, bh3, base + 2 * STG_T + baddr);
                LDSM4(bl0, bl1, bl2, bl3, base + 3 * STG_T + baddr);
                #pragma unroll
                for (int mt = 0; mt < 2; mt++) {
                    float* c0 = c[mt][bg * 2];
                    float* c1 = c[mt][bg * 2 + 1];
                    MMA16816(c0, ah[mt][0], ah[mt][1], ah[mt][2], ah[mt][3], bh0, bh1);
                    MMA16816(c0, ah[mt][0], ah[mt][1], ah[mt][2], ah[mt][3], bl0, bl1);
                    MMA16816(c0, al[mt][0], al[mt][1], al[mt][2], al[mt][3], bh0, bh1);
                    MMA16816(c1, ah[mt][0], ah[mt][1], ah[mt][2], ah[mt][3], bh2, bh3);
                    MMA16816(c1, ah[mt][0], ah[mt][1], ah[mt][2], ah[mt][3], bl2, bl3);
                    MMA16816(c1, al[mt][0], al[mt][1], al[mt][2], al[mt][3], bh2, bh3);
                }
            }
        }
        __syncthreads();
    }
#undef LOAD_STAGE

    const int rbase = bm + wm * 32 + (lane >> 2);
    const int cbase = bn + wn * 64 + (lane & 3) * 2;
    #pragma unroll
    for (int mt = 0; mt < 2; mt++) {
        #pragma unroll
        for (int nt = 0; nt < 8; nt++) {
            int rr = rbase + mt * 16;
            int cc = cbase + nt * 8;
            if (rr < M)
                *(float2*)&C[(size_t)rr * N + cc] = make_float2(c[mt][nt][0], c[mt][nt][1]);
            if (rr + 8 < M)
                *(float2*)&C[(size_t)(rr + 8) * N + cc] = make_float2(c[mt][nt][2], c[mt][nt][3]);
        }
    }
}

// ---------------- layer-1 logits, warp per node, CSR-ordered ---------------
// xr[n] + att register-resident; per in-edge one full-row xl gather.
// float4 q = j*32+lane belongs to head 2j + (lane>=16); 16-lane reductions
// produce heads 2j (lanes 0-15) and 2j+1 (lanes 16-31).
__global__ void k_logits_node10(const float* __restrict__ xl,
                                const float* __restrict__ xr,
                                const int* __restrict__ rowptr,
                                const int* __restrict__ csr_src,
                                const float* __restrict__ att,
                                float* __restrict__ logits)
{
    int n = (blockIdx.x * blockDim.x + threadIdx.x) >> 5;
    int lane = threadIdx.x & 31;
    if (n >= NNODES) return;
    int r0 = rowptr[n], r1 = rowptr[n + 1];

    float4 xr4[5], at4[5];
    const float4* pr = (const float4*)(xr + (size_t)n * HID);
    const float4* pa = (const float4*)att;
    #pragma unroll
    for (int j = 0; j < 5; j++) {
        xr4[j] = pr[j * 32 + lane];
        at4[j] = pa[j * 32 + lane];
    }
    int sub = lane >> 4;            // 0 -> even heads, 1 -> odd heads

    for (int i = r0; i < r1; i++) {
        int s = csr_src[i];
        const float4* ps = (const float4*)(xl + (size_t)s * HID);
        float part[5];
        #pragma unroll
        for (int j = 0; j < 5; j++) {
            float4 x4 = ps[j * 32 + lane];
            float v, sum = 0.f;
            v = x4.x + xr4[j].x; v = v > 0.f ? v : NEGSLOPE * v; sum += v * at4[j].x;
            v = x4.y + xr4[j].y; v = v > 0.f ? v : NEGSLOPE * v; sum += v * at4[j].y;
            v = x4.z + xr4[j].z; v = v > 0.f ? v : NEGSLOPE * v; sum += v * at4[j].z;
            v = x4.w + xr4[j].w; v = v > 0.f ? v : NEGSLOPE * v; sum += v * at4[j].w;
            part[j] = sum;
        }
        #pragma unroll
        for (int o = 8; o > 0; o >>= 1) {
            #pragma unroll
            for (int j = 0; j < 5; j++)
                part[j] += __shfl_xor_sync(0xffffffffu, part[j], o);
        }
        if ((lane & 15) == 0) {
            #pragma unroll
            for (int j = 0; j < 5; j++)
                logits[(size_t)i * HEADS + 2 * j + sub] = part[j];
        }
    }
}

// ---------------- layer-2 logits, warp per node, CSR-ordered ---------------
__global__ void k_logits_node640(const float* __restrict__ xl,
                                 const float* __restrict__ xr,
                                 const int* __restrict__ rowptr,
                                 const int* __restrict__ csr_src,
                                 const float* __restrict__ att,
                                 float* __restrict__ logits)
{
    int n = (blockIdx.x * blockDim.x + threadIdx.x) >> 5;
    int lane = threadIdx.x & 31;
    if (n >= NNODES) return;
    int r0 = rowptr[n], r1 = rowptr[n + 1];

    float4 xr4[5], at4[5];
    const float4* pr = (const float4*)(xr + (size_t)n * HID);
    const float4* pa = (const float4*)att;
    #pragma unroll
    for (int j = 0; j < 5; j++) {
        xr4[j] = pr[j * 32 + lane];
        at4[j] = pa[j * 32 + lane];
    }

    for (int i = r0; i < r1; i++) {
        int s = csr_src[i];
        const float4* ps = (const float4*)(xl + (size_t)s * HID);
        float sum = 0.f;
        #pragma unroll
        for (int j = 0; j < 5; j++) {
            float4 x4 = ps[j * 32 + lane];
            float v;
            v = x4.x + xr4[j].x; v = v > 0.f ? v : NEGSLOPE * v; sum += v * at4[j].x;
            v = x4.y + xr4[j].y; v = v > 0.f ? v : NEGSLOPE * v; sum += v * at4[j].y;
            v = x4.z + xr4[j].z; v = v > 0.f ? v : NEGSLOPE * v; sum += v * at4[j].z;
            v = x4.w + xr4[j].w; v = v > 0.f ? v : NEGSLOPE * v; sum += v * at4[j].w;
        }
        #pragma unroll
        for (int o = 16; o > 0; o >>= 1)
            sum += __shfl_xor_sync(0xffffffffu, sum, o);
        if (lane == 0) logits[i] = sum;
    }
}

// ---------------- GATv2 node aggregate, H=10 Ch=64 (warp per node,head) ----
__global__ void k_gat_node64(const float* __restrict__ xl,
                             const int* __restrict__ rowptr,
                             const int* __restrict__ csr_src,
                             const float* __restrict__ logits,
                             const float* __restrict__ bias,
                             __nv_bfloat16* __restrict__ ohi,
                             __nv_bfloat16* __restrict__ olo)
{
    int gw = (blockIdx.x * blockDim.x + threadIdx.x) >> 5;
    int lane = threadIdx.x & 31;
    if (gw >= NNODES * HEADS) return;
    int n = gw / HEADS, h = gw - n * HEADS;
    int r0 = rowptr[n], r1 = rowptr[n + 1];

    float m = -3.4e38f;
    for (int i = r0 + lane; i < r1; i += 32)
        m = fmaxf(m, logits[(size_t)i * HEADS + h]);
    #pragma unroll
    for (int o = 16; o > 0; o >>= 1)
        m = fmaxf(m, __shfl_xor_sync(0xffffffffu, m, o));

    float den = 0.f, a0 = 0.f, a1 = 0.f;
    int cbase = h * C1 + lane * 2;
    for (int i = r0; i < r1; i++) {
        int s = csr_src[i];
        float ex = expf(logits[(size_t)i * HEADS + h] - m);
        den += ex;
        float2 v = *(const float2*)&xl[(size_t)s * HID + cbase];
        a0 += ex * v.x;
        a1 += ex * v.y;
    }
    float o0 = a0 / den + bias[cbase];
    float o1 = a1 / den + bias[cbase + 1];
    o0 = o0 > 0.f ? o0 : expm1f(o0);
    o1 = o1 > 0.f ? o1 : expm1f(o1);
    __nv_bfloat16 h0 = __float2bfloat16(o0), h1 = __float2bfloat16(o1);
    __nv_bfloat162 hp; hp.x = h0; hp.y = h1;
    __nv_bfloat162 lp;
    lp.x = __float2bfloat16(o0 - __bfloat162float(h0));
    lp.y = __float2bfloat16(o1 - __bfloat162float(h1));
    *(__nv_bfloat162*)&ohi[(size_t)n * HID + cbase] = hp;
    *(__nv_bfloat162*)&olo[(size_t)n * HID + cbase] = lp;
}

// ---------------- GATv2 node aggregate, H=1 Ch=640 (warp per node) ---------
__global__ void k_gat_node640(const float* __restrict__ xl,
                              const int* __restrict__ rowptr,
                              const int* __restrict__ csr_src,
                              const float* __restrict__ logits,
                              const float* __restrict__ bias,
                              __nv_bfloat16* __restrict__ ohi,
                              __nv_bfloat16* __restrict__ olo)
{
    int n = (blockIdx.x * blockDim.x + threadIdx.x) >> 5;
    int lane = threadIdx.x & 31;
    if (n >= NNODES) return;
    int r0 = rowptr[n], r1 = rowptr[n + 1];

    float m = -3.4e38f;
    for (int i = r0 + lane; i < r1; i += 32)
        m = fmaxf(m, logits[i]);
    #pragma unroll
    for (int o = 16; o > 0; o >>= 1)
        m = fmaxf(m, __shfl_xor_sync(0xffffffffu, m, o));

    float den = 0.f;
    float acc[5][4];
    #pragma unroll
    for (int j = 0; j < 5; j++)
        #pragma unroll
        for (int q = 0; q < 4; q++) acc[j][q] = 0.f;

    for (int i = r0; i < r1; i++) {
        int s = csr_src[i];
        float ex = expf(logits[i] - m);
        den += ex;
        const float4* ps = (const float4*)(xl + (size_t)s * HID);
        #pragma unroll
        for (int j = 0; j < 5; j++) {
            float4 v = ps[j * 32 + lane];
            acc[j][0] += ex * v.x;
            acc[j][1] += ex * v.y;
            acc[j][2] += ex * v.z;
            acc[j][3] += ex * v.w;
        }
    }
    float inv = 1.f / den;
    #pragma unroll
    for (int j = 0; j < 5; j++) {
        int cb = (j * 32 + lane) * 4;
        float o0 = acc[j][0] * inv + bias[cb];
        float o1 = acc[j][1] * inv + bias[cb + 1];
        float o2 = acc[j][2] * inv + bias[cb + 2];
        float o3 = acc[j][3] * inv + bias[cb + 3];
        __nv_bfloat16 h0 = __float2bfloat16(o0), h1 = __float2bfloat16(o1);
        __nv_bfloat16 h2 = __float2bfloat16(o2), h3 = __float2bfloat16(o3);
        __nv_bfloat162 hp0; hp0.x = h0; hp0.y = h1;
        __nv_bfloat162 hp1; hp1.x = h2; hp1.y = h3;
        __nv_bfloat162 lp0, lp1;
        lp0.x = __float2bfloat16(o0 - __bfloat162float(h0));
        lp0.y = __float2bfloat16(o1 - __bfloat162float(h1));
        lp1.x = __float2bfloat16(o2 - __bfloat162float(h2));
        lp1.y = __float2bfloat16(o3 - __bfloat162float(h3));
        *(__nv_bfloat162*)&ohi[(size_t)n * HID + cb]     = hp0;
        *(__nv_bfloat162*)&ohi[(size_t)n * HID + cb + 2] = hp1;
        *(__nv_bfloat162*)&olo[(size_t)n * HID + cb]     = lp0;
        *(__nv_bfloat162*)&olo[(size_t)n * HID + cb + 2] = lp1;
    }
}

// ---------------- GCN node aggregate + relu + fused pooling + cnt ----------
__global__ void k_gcn_node(const float* __restrict__ xw,
                           const int* __restrict__ rowptr,
                           const int* __restrict__ csr_src,
                           const float* __restrict__ dinv,
                           const float* __restrict__ bg,
                           const int* __restrict__ batch,
                           int* __restrict__ gmax, float* __restrict__ gsum,
                           float* __restrict__ cnt)
{
    int n = (blockIdx.x * blockDim.x + threadIdx.x) >> 5;
    int lane = threadIdx.x & 31;
    if (n >= NNODES) return;
    int r0 = rowptr[n], r1 = rowptr[n + 1];
    float dv = dinv[n];

    float acc[5][4];
    #pragma unroll
    for (int j = 0; j < 5; j++)
        #pragma unroll
        for (int q = 0; q < 4; q++) acc[j][q] = 0.f;

    for (int i = r0; i < r1; i++) {
        int s = csr_src[i];
        float nrm = dinv[s] * dv;
        const float4* ps = (const float4*)(xw + (size_t)s * HID);
        #pragma unroll
        for (int j = 0; j < 5; j++) {
            float4 v = ps[j * 32 + lane];
            acc[j][0] += nrm * v.x;
            acc[j][1] += nrm * v.y;
            acc[j][2] += nrm * v.z;
            acc[j][3] += nrm * v.w;
        }
    }
    int g = batch[n];
    if (lane == 0) atomicAdd(&cnt[g], 1.f);
    #pragma unroll
    for (int j = 0; j < 5; j++) {
        int cb = (j * 32 + lane) * 4;
        #pragma unroll
        for (int q = 0; q < 4; q++) {
            float o = fmaxf(acc[j][q] + bg[cb + q], 0.f);
            atomicMax(&gmax[g * HID + cb + q], __float_as_int(o));
            atomicAdd(&gsum[g * HID + cb + q], o);
        }
    }
}

// ---------------- pooling tail ---------------------------------------------
__global__ void k_final(const int* __restrict__ gmax, const float* __restrict__ gsum,
                        const float* __restrict__ cnt, float* __restrict__ out)
{
    int idx = blockIdx.x * blockDim.x + threadIdx.x;
    if (idx >= NGRAPH * HID) return;
    int g = idx / HID, c = idx % HID;
    out[(size_t)g * (2 * HID) + c]       = __int_as_float(gmax[idx]);
    out[(size_t)g * (2 * HID) + HID + c] = gsum[idx] / fmaxf(cnt[g], 1.f);
}

// ---------------- launch ---------------------------------------------------
extern "C" void kernel_launch(void* const* d_in, const int* in_sizes, int n_in,
                              void* d_out, int out_size)
{
    const float* x     = (const float*)d_in[0];
    const int*   ei    = (const int*)d_in[1];
    const int*   batch = (const int*)d_in[2];
    const float* Wl1 = (const float*)d_in[3];
    const float* Wr1 = (const float*)d_in[4];
    const float* a1  = (const float*)d_in[5];
    const float* b1  = (const float*)d_in[6];
    const float* Wl2 = (const float*)d_in[7];
    const float* Wr2 = (const float*)d_in[8];
    const float* a2  = (const float*)d_in[9];
    const float* b2  = (const float*)d_in[10];
    const float* Wg  = (const float*)d_in[11];
    const float* bg  = (const float*)d_in[12];
    float* out = (float*)d_out;

    float *A, *B, *logits, *dinv, *gsum, *cnt;
    int *rowptr, *cntbuf, *csr_src, *gmax;
    __nv_bfloat16 *xhi, *xlo, *hhi, *hlo;
    __nv_bfloat16 *w1lhi, *w1llo, *w1rhi, *w1rlo;
    __nv_bfloat16 *w2lhi, *w2llo, *w2rhi, *w2rlo, *wghi, *wglo;
    cudaGetSymbolAddress((void**)&A,       g_bufA);
    cudaGetSymbolAddress((void**)&B,       g_bufB);
    cudaGetSymbolAddress((void**)&logits,  g_logits);
    cudaGetSymbolAddress((void**)&dinv,    g_dinv);
    cudaGetSymbolAddress((void**)&rowptr,  g_rowptr);
    cudaGetSymbolAddress((void**)&cntbuf,  g_cntbuf);
    cudaGetSymbolAddress((void**)&csr_src, g_csr_src);
    cudaGetSymbolAddress((void**)&gmax,    g_gmax);
    cudaGetSymbolAddress((void**)&gsum,    g_gsum);
    cudaGetSymbolAddress((void**)&cnt,     g_cnt);
    cudaGetSymbolAddress((void**)&xhi,     g_xhi);
    cudaGetSymbolAddress((void**)&xlo,     g_xlo);
    cudaGetSymbolAddress((void**)&hhi,     g_hhi);
    cudaGetSymbolAddress((void**)&hlo,     g_hlo);
    cudaGetSymbolAddress((void**)&w1lhi,   g_w1lhi);
    cudaGetSymbolAddress((void**)&w1llo,   g_w1llo);
    cudaGetSymbolAddress((void**)&w1rhi,   g_w1rhi);
    cudaGetSymbolAddress((void**)&w1rlo,   g_w1rlo);
    cudaGetSymbolAddress((void**)&w2lhi,   g_w2lhi);
    cudaGetSymbolAddress((void**)&w2llo,   g_w2llo);
    cudaGetSymbolAddress((void**)&w2rhi,   g_w2rhi);
    cudaGetSymbolAddress((void**)&w2rlo,   g_w2rlo);
    cudaGetSymbolAddress((void**)&wghi,    g_wghi);
    cudaGetSymbolAddress((void**)&wglo,    g_wglo);

    static bool attr_set = false;
    if (!attr_set) {
        cudaFuncSetAttribute(k_hgemm, cudaFuncAttributeMaxDynamicSharedMemorySize, 2 * STG_ALL);
        attr_set = true;
    }

    const int T = 256;
    dim3 gg(HID / 128, (NNODES + 127) / 128);            // (5, 391)
    int nb   = (NNODES + T - 1) / T;
    int epb  = (EPLUS + T - 1) / T;
    int ghb  = (NGRAPH * HID + T - 1) / T;
    int xsb  = (NNODES * KP1 + T - 1) / T;
    int w1b  = (HID * KP1 + T - 1) / T;
    int w2b  = (HID * HID + T - 1) / T;
    int nw64 = (NNODES * HEADS * 32 + T - 1) / T;        // warp per (node,head)
    int nwN  = (NNODES * 32 + T - 1) / T;                // warp per node

    // ---- CSR build (dst-sorted, incl self loops) ----
    k_fill_i<<<nb, T>>>(cntbuf, 0, NNODES);
    k_count<<<epb, T>>>(ei, cntbuf);
    k_scan<<<1, 1024>>>(cntbuf, rowptr);
    k_fill_i<<<nb, T>>>(cntbuf, 0, NNODES);
    k_scatter<<<epb, T>>>(ei, rowptr, cntbuf, csr_src);
    k_dinv<<<nb, T>>>(rowptr, dinv);

    // ---- bf16 hi/lo splits (weights + x) ----
    k_split <<<xsb, T>>>(x, xhi, xlo, NNODES, INDIM, KP1);
    k_splitT<<<w1b, T>>>(Wl1, w1lhi, w1llo, INDIM, HID, KP1);
    k_splitT<<<w1b, T>>>(Wr1, w1rhi, w1rlo, INDIM, HID, KP1);
    k_splitT<<<w2b, T>>>(Wl2, w2lhi, w2llo, HID, HID, HID);
    k_splitT<<<w2b, T>>>(Wr2, w2rhi, w2rlo, HID, HID, HID);
    k_splitT<<<w2b, T>>>(Wg,  wghi,  wglo,  HID, HID, HID);

    // ---- Layer 1: GATv2 (heads=10, C=64) ----
    k_hgemm<<<gg, T, 2 * STG_ALL>>>(xhi, xlo, w1lhi, w1llo, A, NNODES, HID, KP1);
    k_hgemm<<<gg, T, 2 * STG_ALL>>>(xhi, xlo, w1rhi, w1rlo, B, NNODES, HID, KP1);
    k_logits_node10<<<nwN, T>>>(A, B, rowptr, csr_src, a1, logits);
    k_gat_node64<<<nw64, T>>>(A, rowptr, csr_src, logits, b1, hhi, hlo);

    // ---- Layer 2: GATv2 (heads=1, C=640) ----
    k_hgemm<<<gg, T, 2 * STG_ALL>>>(hhi, hlo, w2lhi, w2llo, A, NNODES, HID, HID);
    k_hgemm<<<gg, T, 2 * STG_ALL>>>(hhi, hlo, w2rhi, w2rlo, B, NNODES, HID, HID);
    k_logits_node640<<<nwN, T>>>(A, B, rowptr, csr_src, a2, logits);
    k_gat_node640<<<nwN, T>>>(A, rowptr, csr_src, logits, b2, hhi, hlo);

    // ---- Layer 3: GCN + relu + fused pooling ----
    k_hgemm<<<gg, T, 2 * STG_ALL>>>(hhi, hlo, wghi, wglo, A, NNODES, HID, HID);
    k_pool_init<<<ghb, T>>>(gmax, gsum, cnt);
    k_gcn_node<<<nwN, T>>>(A, rowptr, csr_src, dinv, bg, batch, gmax, gsum, cnt);
    k_final<<<ghb, T>>>(gmax, gsum, cnt, out);
}